// round 13
// baseline (speedup 1.0000x reference)
#include <cuda_runtime.h>
#include <cuda_fp16.h>
#include <cstdint>

#define N_TOK 8192
#define DIMD  1024
#define DIMH  4096
#define DIMO  1024
#define NEXP  8
#define TEMPR 2.718281828459045f

#define MAXSLOTS 17408
#define MAXTILES 136

#define BM 128
#define BN 256
#define BK 64                   // halfs per k-block (4 x m16n8k16)
#define NSTAGE 4
#define STG_A_BYTES (BM * BK * 2)              // 16384
#define STG_B_BYTES (BN * BK * 2)              // 32768
#define STG_BYTES   (STG_A_BYTES + STG_B_BYTES) // 49152
#define SMEM_TOT    (NSTAGE * STG_BYTES)        // 196608

// ---------------- device scratch (static) ----------------
__device__ __half g_hbuf[(size_t)MAXSLOTS * DIMH];
__device__ __half g_xh  [(size_t)N_TOK * DIMD];
__device__ __half g_w1t [(size_t)NEXP * DIMH * DIMD];
__device__ __half g_w2t [(size_t)NEXP * DIMO * DIMH];
__device__ int   g_perm[MAXSLOTS];
__device__ float g_gate[MAXSLOTS];
__device__ int   g_tope[N_TOK * 2];
__device__ float g_topw[N_TOK * 2];
__device__ int   g_cnt[NEXP];
__device__ int   g_cur[NEXP];
__device__ int   g_off[NEXP];
__device__ int   g_texp[MAXTILES];

__device__ __forceinline__ uint32_t smem_u32(const void* p) {
    uint32_t a;
    asm("{ .reg .u64 t; cvta.to.shared.u64 t, %1; cvt.u32.u64 %0, t; }" : "=r"(a) : "l"(p));
    return a;
}
#define CPA16(dst, src) \
    asm volatile("cp.async.cg.shared.global [%0], [%1], 16;" :: "r"(dst), "l"(src))
#define CPA_COMMIT() asm volatile("cp.async.commit_group;" ::: "memory")
#define CPA_WAIT2()  asm volatile("cp.async.wait_group 2;" ::: "memory")
#define CPA_WAIT0()  asm volatile("cp.async.wait_group 0;" ::: "memory")
#define LDSM4(r, a) \
    asm volatile("ldmatrix.sync.aligned.m8n8.x4.shared.b16 {%0,%1,%2,%3}, [%4];" \
        : "=r"((r)[0]), "=r"((r)[1]), "=r"((r)[2]), "=r"((r)[3]) : "r"(a))

// ---------------- one-time converts ----------------
__global__ void k_cvt_x(const float* __restrict__ x) {
    int i = blockIdx.x * blockDim.x + threadIdx.x;
    float4 v = ((const float4*)x)[i];
    __half2* o = (__half2*)&g_xh[(size_t)i * 4];
    o[0] = __floats2half2_rn(v.x, v.y);
    o[1] = __floats2half2_rn(v.z, v.w);
}

template<int K, int N>
__global__ void k_tr(const float* __restrict__ in, __half* __restrict__ out) {
    __shared__ float tile[32][33];
    const int e  = blockIdx.z;
    const int k0 = blockIdx.x * 32;
    const int n0 = blockIdx.y * 32;
    const int tx = threadIdx.x, ty = threadIdx.y;
    const float* src = in + (size_t)e * K * N;
    __half* dst = out + (size_t)e * N * K;
#pragma unroll
    for (int i = 0; i < 4; i++)
        tile[ty + i * 8][tx] = src[(size_t)(k0 + ty + i * 8) * N + n0 + tx];
    __syncthreads();
#pragma unroll
    for (int i = 0; i < 4; i++)
        dst[(size_t)(n0 + ty + i * 8) * K + k0 + tx] = __float2half(tile[tx][ty + i * 8]);
}

// ---------------- routing ----------------
__global__ void k_init() {
    int i = blockIdx.x * blockDim.x + threadIdx.x;
    if (i < MAXSLOTS) { g_perm[i] = -1; g_gate[i] = 0.f; }
    if (i < NEXP)     { g_cnt[i] = 0; g_cur[i] = 0; }
}

__global__ void k_gate(const float* __restrict__ x, const float* __restrict__ Wg,
                       const float* __restrict__ bg) {
    int lane = threadIdx.x & 31;
    int tok  = blockIdx.x * 8 + (threadIdx.x >> 5);
    float acc[NEXP];
#pragma unroll
    for (int e = 0; e < NEXP; e++) acc[e] = 0.f;
    const float* xr = x + (size_t)tok * DIMD;
    for (int d = lane; d < DIMD; d += 32) {
        float xv = xr[d];
        const float4* wg = (const float4*)(Wg + d * NEXP);
        float4 w0 = wg[0], w1 = wg[1];
        acc[0] += xv * w0.x; acc[1] += xv * w0.y; acc[2] += xv * w0.z; acc[3] += xv * w0.w;
        acc[4] += xv * w1.x; acc[5] += xv * w1.y; acc[6] += xv * w1.z; acc[7] += xv * w1.w;
    }
#pragma unroll
    for (int e = 0; e < NEXP; e++) {
#pragma unroll
        for (int o = 16; o > 0; o >>= 1) acc[e] += __shfl_xor_sync(0xffffffffu, acc[e], o);
    }
    if (lane == 0) {
        float s[NEXP];
#pragma unroll
        for (int e = 0; e < NEXP; e++) s[e] = (acc[e] + bg[e]) * (1.0f / TEMPR);
        int i1 = 0;
#pragma unroll
        for (int e = 1; e < NEXP; e++) if (s[e] > s[i1]) i1 = e;
        int i2 = (i1 == 0) ? 1 : 0;
#pragma unroll
        for (int e = 0; e < NEXP; e++) if (e != i1 && s[e] > s[i2]) i2 = e;
        float m = s[i1];
        float denom = 0.f;
#pragma unroll
        for (int e = 0; e < NEXP; e++) denom += expf(s[e] - m);
        float p1 = expf(s[i1] - m) / denom;
        float p2 = expf(s[i2] - m) / denom;
        float inv = 1.f / (p1 + p2 + 1e-8f);
        g_tope[tok * 2 + 0] = i1; g_topw[tok * 2 + 0] = p1 * inv;
        g_tope[tok * 2 + 1] = i2; g_topw[tok * 2 + 1] = p2 * inv;
        atomicAdd(&g_cnt[i1], 1);
        atomicAdd(&g_cnt[i2], 1);
    }
}

__global__ void k_offsets() {
    int tileE[MAXTILES];
    int run = 0;
    for (int e = 0; e < NEXP; e++) {
        g_off[e] = run;
        int ntile = (g_cnt[e] + BM - 1) / BM;
        for (int t = 0; t < ntile; t++) tileE[run / BM + t] = e;
        run += ntile * BM;
    }
    int used = run / BM;
    for (int t = 0; t < MAXTILES; t++) g_texp[t] = (t < used) ? tileE[t] : -1;
}

__global__ void k_scatter() {
    int i = blockIdx.x * blockDim.x + threadIdx.x;
    if (i >= N_TOK * 2) return;
    int e = g_tope[i];
    int pos = atomicAdd(&g_cur[e], 1);
    int slot = g_off[e] + pos;
    g_perm[slot] = i >> 1;
    g_gate[slot] = g_topw[i];
}

// ---------------- fp16 grouped GEMM: 128x256 CTA tile, 8 warps (2Mx4N, 64x64 each) ----------------
template<int KDIM, int NDIM, bool FIRST>
__global__ __launch_bounds__(256, 1) void k_gemm(
    const __half* __restrict__ Bt,
    const float* __restrict__ bias,
    float* __restrict__ Out)
{
    extern __shared__ char smem[];
    const int tileM = blockIdx.y;
    const int e = g_texp[tileM];
    if (e < 0) return;
    const int rowBase = tileM * BM;
    const int colBase = blockIdx.x * BN;

    const uint32_t sb = smem_u32(smem);
    const int tid  = threadIdx.x;
    const int lane = tid & 31;
    const int warp = tid >> 5;
    const int warpM = warp & 1;     // 2 along M
    const int warpN = warp >> 1;    // 4 along N

    // ---- staging maps: thread t -> row (t>>3)+32i, chunk t&7 ----
    const int trow = tid >> 3;      // 0..31
    const int tch  = tid & 7;
    const __half* A = FIRST ? g_xh : g_hbuf;
    const __half* Bmat = Bt + (size_t)e * NDIM * KDIM;

    const __half* aSrc[4];          // A: 128 rows
#pragma unroll
    for (int i = 0; i < 4; i++) {
        int slot = rowBase + trow + 32 * i;
        int src;
        if (FIRST) { int t = g_perm[slot]; src = (t < 0) ? 0 : t; }
        else       { src = slot; }
        aSrc[i] = A + (size_t)src * KDIM + tch * 8;
    }
    const __half* bSrc0 = Bmat + (size_t)(colBase + trow) * KDIM + tch * 8;  // B: 256 rows (+32i)

    uint32_t dOffA[4], dOffB[8];
#pragma unroll
    for (int i = 0; i < 4; i++) {
        int row = trow + 32 * i;
        dOffA[i] = row * 128 + ((tch ^ (row & 7)) << 4);
    }
#pragma unroll
    for (int i = 0; i < 8; i++) {
        int row = trow + 32 * i;
        dOffB[i] = row * 128 + ((tch ^ (row & 7)) << 4);
    }

    // ---- fragment addressing ----
    const int laneRowOff = (lane & 7) + ((lane >> 3) & 1) * 8;
    const int csel = lane >> 4;
    const int xr   = lane & 7;
    uint32_t aRB[4], bRB[4];
#pragma unroll
    for (int mt = 0; mt < 4; mt++) aRB[mt] = (warpM * 64 + mt * 16 + laneRowOff) * 128;
#pragma unroll
    for (int np = 0; np < 4; np++) bRB[np] = (warpN * 64 + np * 16 + laneRowOff) * 128;

    float acc[4][8][4];
#pragma unroll
    for (int mt = 0; mt < 4; mt++)
#pragma unroll
        for (int nt = 0; nt < 8; nt++)
#pragma unroll
            for (int i = 0; i < 4; i++) acc[mt][nt][i] = 0.f;

    const int NKB = KDIM / BK;

    // ---- prologue: issue stages 0..2 ----
#pragma unroll
    for (int s = 0; s < NSTAGE - 1; s++) {
        uint32_t stA = sb + s * STG_BYTES;
        uint32_t stB = stA + STG_A_BYTES;
#pragma unroll
        for (int i = 0; i < 4; i++) CPA16(stA + dOffA[i], aSrc[i] + s * BK);
#pragma unroll
        for (int i = 0; i < 8; i++) CPA16(stB + dOffB[i], bSrc0 + (size_t)(32 * i) * KDIM + s * BK);
        CPA_COMMIT();
    }

    int buf = 0;
    for (int kb = 0; kb < NKB; kb++) {
        CPA_WAIT2();
        __syncthreads();
        if (kb + 3 < NKB) {
            int nb = buf + 3; if (nb >= NSTAGE) nb -= NSTAGE;
            uint32_t stA = sb + nb * STG_BYTES;
            uint32_t stB = stA + STG_A_BYTES;
            const int k0 = (kb + 3) * BK;
#pragma unroll
            for (int i = 0; i < 4; i++) CPA16(stA + dOffA[i], aSrc[i] + k0);
#pragma unroll
            for (int i = 0; i < 8; i++) CPA16(stB + dOffB[i], bSrc0 + (size_t)(32 * i) * KDIM + k0);
        }
        CPA_COMMIT();

        const uint32_t stA = sb + buf * STG_BYTES;
        const uint32_t stB = stA + STG_A_BYTES;
#pragma unroll
        for (int ks = 0; ks < 4; ks++) {
            const uint32_t sw = (uint32_t)(((2 * ks + csel) ^ xr) << 4);
            unsigned af[4][4], bf[4][4];
#pragma unroll
            for (int mt = 0; mt < 4; mt++) LDSM4(af[mt], stA + aRB[mt] + sw);
#pragma unroll
            for (int np = 0; np < 4; np++) LDSM4(bf[np], stB + bRB[np] + sw);
#pragma unroll
            for (int mt = 0; mt < 4; mt++)
#pragma unroll
                for (int nt = 0; nt < 8; nt++) {
                    const unsigned b0 = bf[nt >> 1][nt & 1];
                    const unsigned b1 = bf[nt >> 1][2 + (nt & 1)];
                    asm volatile(
                        "mma.sync.aligned.m16n8k16.row.col.f32.f16.f16.f32 "
                        "{%0,%1,%2,%3},{%4,%5,%6,%7},{%8,%9},{%0,%1,%2,%3};"
                        : "+f"(acc[mt][nt][0]), "+f"(acc[mt][nt][1]),
                          "+f"(acc[mt][nt][2]), "+f"(acc[mt][nt][3])
                        : "r"(af[mt][0]), "r"(af[mt][1]), "r"(af[mt][2]), "r"(af[mt][3]),
                          "r"(b0), "r"(b1));
                }
        }
        buf++; if (buf == NSTAGE) buf = 0;
    }
    CPA_WAIT0();

    // ---------------- epilogue ----------------
    const float* be = bias + (size_t)e * NDIM;
    if (FIRST) {
#pragma unroll
        for (int mt = 0; mt < 4; mt++) {
#pragma unroll
            for (int hh = 0; hh < 2; hh++) {
                int r = rowBase + warpM * 64 + mt * 16 + (lane >> 2) + hh * 8;
#pragma unroll
                for (int nt = 0; nt < 8; nt++) {
                    int c = colBase + warpN * 64 + nt * 8 + (lane & 3) * 2;
                    float v0 = acc[mt][nt][hh * 2 + 0] + be[c];
                    float v1 = acc[mt][nt][hh * 2 + 1] + be[c + 1];
                    v0 = v0 > 0.f ? v0 : 0.f;
                    v1 = v1 > 0.f ? v1 : 0.f;
                    *(__half2*)&g_hbuf[(size_t)r * DIMH + c] = __floats2half2_rn(v0, v1);
                }
            }
        }
    } else {
#pragma unroll
        for (int mt = 0; mt < 4; mt++) {
#pragma unroll
            for (int hh = 0; hh < 2; hh++) {
                int slot = rowBase + warpM * 64 + mt * 16 + (lane >> 2) + hh * 8;
                int tokn = g_perm[slot];
                if (tokn < 0) continue;
                float w = g_gate[slot];
#pragma unroll
                for (int nt = 0; nt < 8; nt++) {
                    int c = colBase + warpN * 64 + nt * 8 + (lane & 3) * 2;
                    atomicAdd(&Out[(size_t)tokn * DIMO + c],
                              w * (acc[mt][nt][hh * 2 + 0] + be[c]));
                    atomicAdd(&Out[(size_t)tokn * DIMO + c + 1],
                              w * (acc[mt][nt][hh * 2 + 1] + be[c + 1]));
                }
            }
        }
    }
}

// ---------------- launch ----------------
extern "C" void kernel_launch(void* const* d_in, const int* in_sizes, int n_in,
                              void* d_out, int out_size) {
    const float* x  = (const float*)d_in[0];
    const float* Wg = (const float*)d_in[1];
    const float* bg = (const float*)d_in[2];
    const float* W1 = (const float*)d_in[3];
    const float* b1 = (const float*)d_in[4];
    const float* W2 = (const float*)d_in[5];
    const float* b2 = (const float*)d_in[6];
    float* out = (float*)d_out;

    __half *w1t, *w2t;
    cudaGetSymbolAddress((void**)&w1t, g_w1t);
    cudaGetSymbolAddress((void**)&w2t, g_w2t);

    cudaFuncSetAttribute(k_gemm<DIMD, DIMH, true>,
                         cudaFuncAttributeMaxDynamicSharedMemorySize, SMEM_TOT);
    cudaFuncSetAttribute(k_gemm<DIMH, DIMO, false>,
                         cudaFuncAttributeMaxDynamicSharedMemorySize, SMEM_TOT);

    cudaMemsetAsync(d_out, 0, (size_t)N_TOK * DIMO * sizeof(float));
    // routing first, then converts, then GEMMs — also moves k_gemm into the
    // ncu sampling window for the next profile.
    k_init<<<(MAXSLOTS + 255) / 256, 256>>>();
    k_gate<<<N_TOK / 8, 256>>>(x, Wg, bg);
    k_offsets<<<1, 1>>>();
    k_scatter<<<(N_TOK * 2 + 255) / 256, 256>>>();
    k_cvt_x<<<(N_TOK * DIMD / 4 + 255) / 256, 256>>>(x);
    k_tr<DIMD, DIMH><<<dim3(DIMD / 32, DIMH / 32, NEXP), dim3(32, 8)>>>(W1, w1t);
    k_gemm<DIMD, DIMH, true ><<<dim3(DIMH / BN, MAXTILES), 256, SMEM_TOT>>>(w1t, b1, nullptr);
    k_tr<DIMH, DIMO><<<dim3(DIMH / 32, DIMO / 32, NEXP), dim3(32, 8)>>>(W2, w2t);
    k_gemm<DIMH, DIMO, false><<<dim3(DIMO / BN, MAXTILES), 256, SMEM_TOT>>>(w2t, b2, out);
}

// round 15
// speedup vs baseline: 1.6603x; 1.6603x over previous
#include <cuda_runtime.h>
#include <cuda_fp16.h>
#include <cstdint>

#define N_TOK 8192
#define DIMD  1024
#define DIMH  4096
#define DIMO  1024
#define NEXP  8
#define TEMPR 2.718281828459045f

#define MAXSLOTS 17408
#define MAXTILES 136

#define BM 128
#define BN 128
#define BK 64
#define NSTAGE 3
#define STG_A_BYTES (BM * BK * 2)          // 16384
#define STG_BYTES   (2 * STG_A_BYTES)      // 32768
#define SMEM_TOT    (NSTAGE * STG_BYTES)   // 98304

// ---------------- device scratch (static) ----------------
__device__ __half g_hbuf[(size_t)MAXSLOTS * DIMH];
__device__ __half g_xh  [(size_t)N_TOK * DIMD];
__device__ __half g_w1t [(size_t)NEXP * DIMH * DIMD];
__device__ __half g_w2t [(size_t)NEXP * DIMO * DIMH];
__device__ int   g_perm[MAXSLOTS];
__device__ float g_gate[MAXSLOTS];
__device__ int   g_tope[N_TOK * 2];
__device__ float g_topw[N_TOK * 2];
__device__ int   g_cnt[NEXP];
__device__ int   g_cur[NEXP];
__device__ int   g_off[NEXP];
__device__ int   g_texp[MAXTILES];

__device__ __forceinline__ uint32_t smem_u32(const void* p) {
    uint32_t a;
    asm("{ .reg .u64 t; cvta.to.shared.u64 t, %1; cvt.u32.u64 %0, t; }" : "=r"(a) : "l"(p));
    return a;
}
#define CPA16(dst, src) \
    asm volatile("cp.async.cg.shared.global [%0], [%1], 16;" :: "r"(dst), "l"(src))
#define CPA_COMMIT() asm volatile("cp.async.commit_group;" ::: "memory")
#define CPA_WAIT1()  asm volatile("cp.async.wait_group 1;" ::: "memory")
#define CPA_WAIT0()  asm volatile("cp.async.wait_group 0;" ::: "memory")
#define LDSM4(r, a) \
    asm volatile("ldmatrix.sync.aligned.m8n8.x4.shared.b16 {%0,%1,%2,%3}, [%4];" \
        : "=r"((r)[0]), "=r"((r)[1]), "=r"((r)[2]), "=r"((r)[3]) : "r"(a))

// ---------------- init: zero out, counters, perm/gate ----------------
__global__ void k_init(float* __restrict__ out) {
    int i = blockIdx.x * blockDim.x + threadIdx.x;
    // zero d_out as float4 (N_TOK*DIMO/4 = 2M float4)
    if (i < N_TOK * DIMO / 4) ((float4*)out)[i] = make_float4(0.f, 0.f, 0.f, 0.f);
    if (i < MAXSLOTS) { g_perm[i] = -1; g_gate[i] = 0.f; }
    if (i < NEXP)     { g_cnt[i] = 0; g_cur[i] = 0; }
}

// transpose+convert: in [E][K][N] fp32 -> out [E][N][K] half
template<int K, int N>
__global__ void k_tr(const float* __restrict__ in, __half* __restrict__ out) {
    __shared__ float tile[32][33];
    const int e  = blockIdx.z;
    const int k0 = blockIdx.x * 32;
    const int n0 = blockIdx.y * 32;
    const int tx = threadIdx.x, ty = threadIdx.y;
    const float* src = in + (size_t)e * K * N;
    __half* dst = out + (size_t)e * N * K;
#pragma unroll
    for (int i = 0; i < 4; i++)
        tile[ty + i * 8][tx] = src[(size_t)(k0 + ty + i * 8) * N + n0 + tx];
    __syncthreads();
#pragma unroll
    for (int i = 0; i < 4; i++)
        dst[(size_t)(n0 + ty + i * 8) * K + k0 + tx] = __float2half(tile[tx][ty + i * 8]);
}

// ---------------- gating + x->half conversion (fused) ----------------
__global__ void k_gate(const float* __restrict__ x, const float* __restrict__ Wg,
                       const float* __restrict__ bg) {
    int lane = threadIdx.x & 31;
    int tok  = blockIdx.x * 8 + (threadIdx.x >> 5);
    float acc[NEXP];
#pragma unroll
    for (int e = 0; e < NEXP; e++) acc[e] = 0.f;
    const float* xr = x + (size_t)tok * DIMD;
    for (int d = lane; d < DIMD; d += 32) {
        float xv = xr[d];
        g_xh[(size_t)tok * DIMD + d] = __float2half(xv);      // fused convert
        const float4* wg = (const float4*)(Wg + d * NEXP);
        float4 w0 = wg[0], w1 = wg[1];
        acc[0] += xv * w0.x; acc[1] += xv * w0.y; acc[2] += xv * w0.z; acc[3] += xv * w0.w;
        acc[4] += xv * w1.x; acc[5] += xv * w1.y; acc[6] += xv * w1.z; acc[7] += xv * w1.w;
    }
#pragma unroll
    for (int e = 0; e < NEXP; e++) {
#pragma unroll
        for (int o = 16; o > 0; o >>= 1) acc[e] += __shfl_xor_sync(0xffffffffu, acc[e], o);
    }
    if (lane == 0) {
        float s[NEXP];
#pragma unroll
        for (int e = 0; e < NEXP; e++) s[e] = (acc[e] + bg[e]) * (1.0f / TEMPR);
        int i1 = 0;
#pragma unroll
        for (int e = 1; e < NEXP; e++) if (s[e] > s[i1]) i1 = e;
        int i2 = (i1 == 0) ? 1 : 0;
#pragma unroll
        for (int e = 0; e < NEXP; e++) if (e != i1 && s[e] > s[i2]) i2 = e;
        float m = s[i1];
        float denom = 0.f;
#pragma unroll
        for (int e = 0; e < NEXP; e++) denom += expf(s[e] - m);
        float p1 = expf(s[i1] - m) / denom;
        float p2 = expf(s[i2] - m) / denom;
        float inv = 1.f / (p1 + p2 + 1e-8f);
        g_tope[tok * 2 + 0] = i1; g_topw[tok * 2 + 0] = p1 * inv;
        g_tope[tok * 2 + 1] = i2; g_topw[tok * 2 + 1] = p2 * inv;
        atomicAdd(&g_cnt[i1], 1);
        atomicAdd(&g_cnt[i2], 1);
    }
}

// ---------------- route: offsets + scatter in one single-block kernel ----------------
__global__ void k_route() {
    const int tid = threadIdx.x;
    if (tid == 0) {
        int tileE[MAXTILES];
        int run = 0;
        for (int e = 0; e < NEXP; e++) {
            g_off[e] = run;
            int ntile = (g_cnt[e] + BM - 1) / BM;
            for (int t = 0; t < ntile; t++) tileE[run / BM + t] = e;
            run += ntile * BM;
        }
        int used = run / BM;
        for (int t = 0; t < MAXTILES; t++) g_texp[t] = (t < used) ? tileE[t] : -1;
    }
    __syncthreads();
    for (int i = tid; i < N_TOK * 2; i += blockDim.x) {
        int e = g_tope[i];
        int pos = atomicAdd(&g_cur[e], 1);
        int slot = g_off[e] + pos;
        g_perm[slot] = i >> 1;
        g_gate[slot] = g_topw[i];
    }
}

// ---------------- fp16 grouped GEMM: 128 threads, warp tile 64x64 (R12 champion) ----------------
template<int KDIM, int NDIM, bool FIRST>
__global__ __launch_bounds__(128, 2) void k_gemm(
    const __half* __restrict__ Bt,
    const float* __restrict__ bias,
    float* __restrict__ Out)
{
    extern __shared__ char smem[];
    const int tileM = blockIdx.y;
    const int e = g_texp[tileM];
    if (e < 0) return;
    const int rowBase = tileM * BM;
    const int colBase = blockIdx.x * BN;

    const uint32_t sb = smem_u32(smem);
    const int tid  = threadIdx.x;
    const int lane = tid & 31;
    const int warp = tid >> 5;
    const int warpM = warp & 1;
    const int warpN = warp >> 1;

    const int trow = tid >> 3;
    const int tch  = tid & 7;
    const __half* A = FIRST ? g_xh : g_hbuf;
    const __half* Bmat = Bt + (size_t)e * NDIM * KDIM;

    const __half* aSrc[8];
#pragma unroll
    for (int i = 0; i < 8; i++) {
        int slot = rowBase + trow + 16 * i;
        int src;
        if (FIRST) { int t = g_perm[slot]; src = (t < 0) ? 0 : t; }
        else       { src = slot; }
        aSrc[i] = A + (size_t)src * KDIM + tch * 8;
    }
    const __half* bSrc0 = Bmat + (size_t)(colBase + trow) * KDIM + tch * 8;

    uint32_t dOff[8];
#pragma unroll
    for (int i = 0; i < 8; i++) {
        int row = trow + 16 * i;
        dOff[i] = row * 128 + ((tch ^ (row & 7)) << 4);
    }

    const int laneRowOff = (lane & 7) + ((lane >> 3) & 1) * 8;
    const int csel = lane >> 4;
    const int xr   = lane & 7;
    uint32_t aRB[4], bRB[4];
#pragma unroll
    for (int mt = 0; mt < 4; mt++) aRB[mt] = (warpM * 64 + mt * 16 + laneRowOff) * 128;
#pragma unroll
    for (int np = 0; np < 4; np++) bRB[np] = (warpN * 64 + np * 16 + laneRowOff) * 128;

    float acc[4][8][4];
#pragma unroll
    for (int mt = 0; mt < 4; mt++)
#pragma unroll
        for (int nt = 0; nt < 8; nt++)
#pragma unroll
            for (int i = 0; i < 4; i++) acc[mt][nt][i] = 0.f;

    const int NKB = KDIM / BK;

#pragma unroll
    for (int s = 0; s < NSTAGE - 1; s++) {
        uint32_t stA = sb + s * STG_BYTES;
        uint32_t stB = stA + STG_A_BYTES;
#pragma unroll
        for (int i = 0; i < 8; i++) CPA16(stA + dOff[i], aSrc[i] + s * BK);
#pragma unroll
        for (int i = 0; i < 8; i++) CPA16(stB + dOff[i], bSrc0 + (size_t)(16 * i) * KDIM + s * BK);
        CPA_COMMIT();
    }

    int buf = 0;
    for (int kb = 0; kb < NKB; kb++) {
        CPA_WAIT1();
        __syncthreads();
        if (kb + 2 < NKB) {
            int nb = buf + 2; if (nb >= NSTAGE) nb -= NSTAGE;
            uint32_t stA = sb + nb * STG_BYTES;
            uint32_t stB = stA + STG_A_BYTES;
            const int k0 = (kb + 2) * BK;
#pragma unroll
            for (int i = 0; i < 8; i++) CPA16(stA + dOff[i], aSrc[i] + k0);
#pragma unroll
            for (int i = 0; i < 8; i++) CPA16(stB + dOff[i], bSrc0 + (size_t)(16 * i) * KDIM + k0);
        }
        CPA_COMMIT();

        const uint32_t stA = sb + buf * STG_BYTES;
        const uint32_t stB = stA + STG_A_BYTES;
#pragma unroll
        for (int ks = 0; ks < 4; ks++) {
            const uint32_t sw = (uint32_t)(((2 * ks + csel) ^ xr) << 4);
            unsigned af[4][4], bf[4][4];
#pragma unroll
            for (int mt = 0; mt < 4; mt++) LDSM4(af[mt], stA + aRB[mt] + sw);
#pragma unroll
            for (int np = 0; np < 4; np++) LDSM4(bf[np], stB + bRB[np] + sw);
#pragma unroll
            for (int mt = 0; mt < 4; mt++)
#pragma unroll
                for (int nt = 0; nt < 8; nt++) {
                    const unsigned b0 = bf[nt >> 1][nt & 1];
                    const unsigned b1 = bf[nt >> 1][2 + (nt & 1)];
                    asm volatile(
                        "mma.sync.aligned.m16n8k16.row.col.f32.f16.f16.f32 "
                        "{%0,%1,%2,%3},{%4,%5,%6,%7},{%8,%9},{%0,%1,%2,%3};"
                        : "+f"(acc[mt][nt][0]), "+f"(acc[mt][nt][1]),
                          "+f"(acc[mt][nt][2]), "+f"(acc[mt][nt][3])
                        : "r"(af[mt][0]), "r"(af[mt][1]), "r"(af[mt][2]), "r"(af[mt][3]),
                          "r"(b0), "r"(b1));
                }
        }
        buf++; if (buf == NSTAGE) buf = 0;
    }
    CPA_WAIT0();

    // ---------------- epilogue ----------------
    const float* be = bias + (size_t)e * NDIM;
    if (FIRST) {
#pragma unroll
        for (int mt = 0; mt < 4; mt++) {
#pragma unroll
            for (int hh = 0; hh < 2; hh++) {
                int r = rowBase + warpM * 64 + mt * 16 + (lane >> 2) + hh * 8;
#pragma unroll
                for (int nt = 0; nt < 8; nt++) {
                    int c = colBase + warpN * 64 + nt * 8 + (lane & 3) * 2;
                    float v0 = acc[mt][nt][hh * 2 + 0] + be[c];
                    float v1 = acc[mt][nt][hh * 2 + 1] + be[c + 1];
                    v0 = v0 > 0.f ? v0 : 0.f;
                    v1 = v1 > 0.f ? v1 : 0.f;
                    *(__half2*)&g_hbuf[(size_t)r * DIMH + c] = __floats2half2_rn(v0, v1);
                }
            }
        }
    } else {
#pragma unroll
        for (int mt = 0; mt < 4; mt++) {
#pragma unroll
            for (int hh = 0; hh < 2; hh++) {
                int slot = rowBase + warpM * 64 + mt * 16 + (lane >> 2) + hh * 8;
                int tokn = g_perm[slot];
                if (tokn < 0) continue;
                float w = g_gate[slot];
#pragma unroll
                for (int nt = 0; nt < 8; nt++) {
                    int c = colBase + warpN * 64 + nt * 8 + (lane & 3) * 2;
                    atomicAdd(&Out[(size_t)tokn * DIMO + c],
                              w * (acc[mt][nt][hh * 2 + 0] + be[c]));
                    atomicAdd(&Out[(size_t)tokn * DIMO + c + 1],
                              w * (acc[mt][nt][hh * 2 + 1] + be[c + 1]));
                }
            }
        }
    }
}

// ---------------- launch ----------------
// order matters for ncu (-s 5 captures the 5th node): init(1), tr_W1(2),
// gate_cvt(3), route(4), gemm1(5) <- profiled
extern "C" void kernel_launch(void* const* d_in, const int* in_sizes, int n_in,
                              void* d_out, int out_size) {
    const float* x  = (const float*)d_in[0];
    const float* Wg = (const float*)d_in[1];
    const float* bg = (const float*)d_in[2];
    const float* W1 = (const float*)d_in[3];
    const float* b1 = (const float*)d_in[4];
    const float* W2 = (const float*)d_in[5];
    const float* b2 = (const float*)d_in[6];
    float* out = (float*)d_out;

    __half *w1t, *w2t;
    cudaGetSymbolAddress((void**)&w1t, g_w1t);
    cudaGetSymbolAddress((void**)&w2t, g_w2t);

    cudaFuncSetAttribute(k_gemm<DIMD, DIMH, true>,
                         cudaFuncAttributeMaxDynamicSharedMemorySize, SMEM_TOT);
    cudaFuncSetAttribute(k_gemm<DIMH, DIMO, false>,
                         cudaFuncAttributeMaxDynamicSharedMemorySize, SMEM_TOT);

    k_init<<<(N_TOK * DIMO / 4 + 255) / 256, 256>>>(out);
    k_tr<DIMD, DIMH><<<dim3(DIMD / 32, DIMH / 32, NEXP), dim3(32, 8)>>>(W1, w1t);
    k_gate<<<N_TOK / 8, 256>>>(x, Wg, bg);
    k_route<<<1, 1024>>>();
    k_gemm<DIMD, DIMH, true ><<<dim3(DIMH / BN, MAXTILES), 128, SMEM_TOT>>>(w1t, b1, nullptr);
    k_tr<DIMH, DIMO><<<dim3(DIMH / 32, DIMO / 32, NEXP), dim3(32, 8)>>>(W2, w2t);
    k_gemm<DIMH, DIMO, false><<<dim3(DIMO / BN, MAXTILES), 128, SMEM_TOT>>>(w2t, b2, out);
}

// round 16
// speedup vs baseline: 2.0038x; 1.2069x over previous
#include <cuda_runtime.h>
#include <cuda_fp16.h>
#include <cstdint>

#define N_TOK 8192
#define DIMD  1024
#define DIMH  4096
#define DIMO  1024
#define NEXP  8
#define TEMPR 2.718281828459045f

#define MAXSLOTS 17408
#define MAXTILES 136

#define BM 128
#define BN 128
#define BK 64
#define NSTAGE 3
#define STG_A_BYTES (BM * BK * 2)          // 16384 (A: 128 rows x 128B)
#define STG_B_BYTES (BK * BN * 2)          // 16384 (B: 64 k-rows x 256B)
#define STG_BYTES   (STG_A_BYTES + STG_B_BYTES)
#define SMEM_TOT    (NSTAGE * STG_BYTES)   // 98304

// ---------------- device scratch (static) ----------------
__device__ __half g_hbuf[(size_t)MAXSLOTS * DIMH];
__device__ __half g_xh  [(size_t)N_TOK * DIMD];
__device__ __half g_w1h [(size_t)NEXP * DIMD * DIMH];   // W1 half, SAME [E][D][H] layout
__device__ __half g_w2h [(size_t)NEXP * DIMH * DIMO];   // W2 half, SAME [E][H][O] layout
__device__ int   g_perm[MAXSLOTS];
__device__ float g_gate[MAXSLOTS];
__device__ int   g_tope[N_TOK * 2];
__device__ float g_topw[N_TOK * 2];
__device__ int   g_cnt[NEXP];
__device__ int   g_cur[NEXP];
__device__ int   g_off[NEXP];
__device__ int   g_texp[MAXTILES];

__device__ __forceinline__ uint32_t smem_u32(const void* p) {
    uint32_t a;
    asm("{ .reg .u64 t; cvta.to.shared.u64 t, %1; cvt.u32.u64 %0, t; }" : "=r"(a) : "l"(p));
    return a;
}
#define CPA16(dst, src) \
    asm volatile("cp.async.cg.shared.global [%0], [%1], 16;" :: "r"(dst), "l"(src))
#define CPA_COMMIT() asm volatile("cp.async.commit_group;" ::: "memory")
#define CPA_WAIT1()  asm volatile("cp.async.wait_group 1;" ::: "memory")
#define CPA_WAIT0()  asm volatile("cp.async.wait_group 0;" ::: "memory")
#define LDSM4(r, a) \
    asm volatile("ldmatrix.sync.aligned.m8n8.x4.shared.b16 {%0,%1,%2,%3}, [%4];" \
        : "=r"((r)[0]), "=r"((r)[1]), "=r"((r)[2]), "=r"((r)[3]) : "r"(a))
#define LDSM4T(r, a) \
    asm volatile("ldmatrix.sync.aligned.m8n8.x4.trans.shared.b16 {%0,%1,%2,%3}, [%4];" \
        : "=r"((r)[0]), "=r"((r)[1]), "=r"((r)[2]), "=r"((r)[3]) : "r"(a))

// ---------------- init: zero d_out, counters, perm/gate ----------------
__global__ void k_init(float* __restrict__ out) {
    int i = blockIdx.x * blockDim.x + threadIdx.x;
    if (i < N_TOK * DIMO / 4) ((float4*)out)[i] = make_float4(0.f, 0.f, 0.f, 0.f);
    if (i < MAXSLOTS) { g_perm[i] = -1; g_gate[i] = 0.f; }
    if (i < NEXP)     { g_cnt[i] = 0; g_cur[i] = 0; }
}

// ---------------- pure streaming convert fp32 -> fp16 (8 elems/thread, 16B out) ----------------
__global__ void k_cvt(const float4* __restrict__ in, uint4* __restrict__ out, int n8) {
    int i = blockIdx.x * blockDim.x + threadIdx.x;
    if (i >= n8) return;
    float4 a = in[2 * i], b = in[2 * i + 1];
    __half2 h[4];
    h[0] = __floats2half2_rn(a.x, a.y);
    h[1] = __floats2half2_rn(a.z, a.w);
    h[2] = __floats2half2_rn(b.x, b.y);
    h[3] = __floats2half2_rn(b.z, b.w);
    out[i] = *(uint4*)h;
}

// ---------------- routing (R12-proven) ----------------
__global__ void k_gate(const float* __restrict__ x, const float* __restrict__ Wg,
                       const float* __restrict__ bg) {
    int lane = threadIdx.x & 31;
    int tok  = blockIdx.x * 8 + (threadIdx.x >> 5);
    float acc[NEXP];
#pragma unroll
    for (int e = 0; e < NEXP; e++) acc[e] = 0.f;
    const float* xr = x + (size_t)tok * DIMD;
    for (int d = lane; d < DIMD; d += 32) {
        float xv = xr[d];
        const float4* wg = (const float4*)(Wg + d * NEXP);
        float4 w0 = wg[0], w1 = wg[1];
        acc[0] += xv * w0.x; acc[1] += xv * w0.y; acc[2] += xv * w0.z; acc[3] += xv * w0.w;
        acc[4] += xv * w1.x; acc[5] += xv * w1.y; acc[6] += xv * w1.z; acc[7] += xv * w1.w;
    }
#pragma unroll
    for (int e = 0; e < NEXP; e++) {
#pragma unroll
        for (int o = 16; o > 0; o >>= 1) acc[e] += __shfl_xor_sync(0xffffffffu, acc[e], o);
    }
    if (lane == 0) {
        float s[NEXP];
#pragma unroll
        for (int e = 0; e < NEXP; e++) s[e] = (acc[e] + bg[e]) * (1.0f / TEMPR);
        int i1 = 0;
#pragma unroll
        for (int e = 1; e < NEXP; e++) if (s[e] > s[i1]) i1 = e;
        int i2 = (i1 == 0) ? 1 : 0;
#pragma unroll
        for (int e = 0; e < NEXP; e++) if (e != i1 && s[e] > s[i2]) i2 = e;
        float m = s[i1];
        float denom = 0.f;
#pragma unroll
        for (int e = 0; e < NEXP; e++) denom += expf(s[e] - m);
        float p1 = expf(s[i1] - m) / denom;
        float p2 = expf(s[i2] - m) / denom;
        float inv = 1.f / (p1 + p2 + 1e-8f);
        g_tope[tok * 2 + 0] = i1; g_topw[tok * 2 + 0] = p1 * inv;
        g_tope[tok * 2 + 1] = i2; g_topw[tok * 2 + 1] = p2 * inv;
        atomicAdd(&g_cnt[i1], 1);
        atomicAdd(&g_cnt[i2], 1);
    }
}

__global__ void k_offsets() {
    int tileE[MAXTILES];
    int run = 0;
    for (int e = 0; e < NEXP; e++) {
        g_off[e] = run;
        int ntile = (g_cnt[e] + BM - 1) / BM;
        for (int t = 0; t < ntile; t++) tileE[run / BM + t] = e;
        run += ntile * BM;
    }
    int used = run / BM;
    for (int t = 0; t < MAXTILES; t++) g_texp[t] = (t < used) ? tileE[t] : -1;
}

__global__ void k_scatter() {
    int i = blockIdx.x * blockDim.x + threadIdx.x;
    if (i >= N_TOK * 2) return;
    int e = g_tope[i];
    int pos = atomicAdd(&g_cur[e], 1);
    int slot = g_off[e] + pos;
    g_perm[slot] = i >> 1;
    g_gate[slot] = g_topw[i];
}

// ---------------- fp16 grouped GEMM ----------------
// A [m][k] smem tile (128 rows x 128B), frag via LDSM4 (as R12).
// B kept in ORIGINAL [k][n] layout: smem tile 64 k-rows x 256B, frag via LDSM4T
// (ldmatrix.trans), eliminating the transpose pre-pass.
template<int KDIM, int NDIM, bool FIRST>
__global__ __launch_bounds__(128, 2) void k_gemm(
    const __half* __restrict__ Bh,
    const float* __restrict__ bias,
    float* __restrict__ Out)
{
    extern __shared__ char smem[];
    const int tileM = blockIdx.y;
    const int e = g_texp[tileM];
    if (e < 0) return;
    const int rowBase = tileM * BM;
    const int colBase = blockIdx.x * BN;

    const uint32_t sb = smem_u32(smem);
    const int tid  = threadIdx.x;
    const int lane = tid & 31;
    const int warp = tid >> 5;
    const int warpM = warp & 1;
    const int warpN = warp >> 1;

    const __half* A = FIRST ? g_xh : g_hbuf;
    const __half* Bmat = Bh + (size_t)e * KDIM * NDIM;   // [K][N], row stride NDIM

    // ---- A staging: thread t -> rows (t>>3)+16i, chunk t&7 (8 chunks of 16B per 128B row) ----
    const int trow = tid >> 3;
    const int tch  = tid & 7;
    const __half* aSrc[8];
#pragma unroll
    for (int i = 0; i < 8; i++) {
        int slot = rowBase + trow + 16 * i;
        int src;
        if (FIRST) { int t = g_perm[slot]; src = (t < 0) ? 0 : t; }
        else       { src = slot; }
        aSrc[i] = A + (size_t)src * KDIM + tch * 8;
    }
    uint32_t dOffA[8];
#pragma unroll
    for (int i = 0; i < 8; i++) {
        int row = trow + 16 * i;
        dOffA[i] = row * 128 + ((tch ^ (row & 7)) << 4);
    }

    // ---- B staging: thread t -> k-rows (t>>4)+8i, chunk t&15 (16 chunks of 16B per 256B row) ----
    const int bR8 = tid >> 4;       // 0..7
    const int bC  = tid & 15;
    const __half* bSrc[8];
    uint32_t dOffB[8];
#pragma unroll
    for (int i = 0; i < 8; i++) {
        int krow = bR8 + 8 * i;
        bSrc[i] = Bmat + (size_t)krow * NDIM + colBase + bC * 8;
        dOffB[i] = krow * 256 + ((bC ^ (krow & 7)) << 4);
    }

    // ---- fragment addressing ----
    const int laneRowOff = (lane & 7) + ((lane >> 3) & 1) * 8;
    const int csel = lane >> 4;
    const int xr   = lane & 7;
    uint32_t aRB[4];
#pragma unroll
    for (int mt = 0; mt < 4; mt++) aRB[mt] = (warpM * 64 + mt * 16 + laneRowOff) * 128;
    // B: chunk index = warpN*8 + ((np*2 + csel) ^ xr); row = ks*16 + laneRowOff
    uint32_t bCh[4];
#pragma unroll
    for (int np = 0; np < 4; np++)
        bCh[np] = (uint32_t)((warpN * 8 + ((np * 2 + csel) ^ xr)) << 4);
    const uint32_t bRowOff = (uint32_t)(laneRowOff * 256);

    float acc[4][8][4];
#pragma unroll
    for (int mt = 0; mt < 4; mt++)
#pragma unroll
        for (int nt = 0; nt < 8; nt++)
#pragma unroll
            for (int i = 0; i < 4; i++) acc[mt][nt][i] = 0.f;

    const int NKB = KDIM / BK;

#pragma unroll
    for (int s = 0; s < NSTAGE - 1; s++) {
        uint32_t stA = sb + s * STG_BYTES;
        uint32_t stB = stA + STG_A_BYTES;
#pragma unroll
        for (int i = 0; i < 8; i++) CPA16(stA + dOffA[i], aSrc[i] + s * BK);
#pragma unroll
        for (int i = 0; i < 8; i++) CPA16(stB + dOffB[i], bSrc[i] + (size_t)s * BK * NDIM);
        CPA_COMMIT();
    }

    int buf = 0;
    for (int kb = 0; kb < NKB; kb++) {
        CPA_WAIT1();
        __syncthreads();
        if (kb + 2 < NKB) {
            int nb = buf + 2; if (nb >= NSTAGE) nb -= NSTAGE;
            uint32_t stA = sb + nb * STG_BYTES;
            uint32_t stB = stA + STG_A_BYTES;
            const int k0 = (kb + 2) * BK;
#pragma unroll
            for (int i = 0; i < 8; i++) CPA16(stA + dOffA[i], aSrc[i] + k0);
#pragma unroll
            for (int i = 0; i < 8; i++) CPA16(stB + dOffB[i], bSrc[i] + (size_t)k0 * NDIM);
        }
        CPA_COMMIT();

        const uint32_t stA = sb + buf * STG_BYTES;
        const uint32_t stB = stA + STG_A_BYTES;
#pragma unroll
        for (int ks = 0; ks < 4; ks++) {
            const uint32_t swA = (uint32_t)(((2 * ks + csel) ^ xr) << 4);
            const uint32_t rB  = (uint32_t)(ks * 16 * 256) + bRowOff;
            unsigned af[4][4], bf[4][4];
#pragma unroll
            for (int mt = 0; mt < 4; mt++) LDSM4(af[mt], stA + aRB[mt] + swA);
#pragma unroll
            for (int np = 0; np < 4; np++) LDSM4T(bf[np], stB + rB + bCh[np]);
#pragma unroll
            for (int mt = 0; mt < 4; mt++)
#pragma unroll
                for (int nt = 0; nt < 8; nt++) {
                    // trans regs: {0,1} = n-sub 0 (k lo, k hi), {2,3} = n-sub 8
                    const unsigned b0 = bf[nt >> 1][(nt & 1) * 2];
                    const unsigned b1 = bf[nt >> 1][(nt & 1) * 2 + 1];
                    asm volatile(
                        "mma.sync.aligned.m16n8k16.row.col.f32.f16.f16.f32 "
                        "{%0,%1,%2,%3},{%4,%5,%6,%7},{%8,%9},{%0,%1,%2,%3};"
                        : "+f"(acc[mt][nt][0]), "+f"(acc[mt][nt][1]),
                          "+f"(acc[mt][nt][2]), "+f"(acc[mt][nt][3])
                        : "r"(af[mt][0]), "r"(af[mt][1]), "r"(af[mt][2]), "r"(af[mt][3]),
                          "r"(b0), "r"(b1));
                }
        }
        buf++; if (buf == NSTAGE) buf = 0;
    }
    CPA_WAIT0();

    // ---------------- epilogue ----------------
    const float* be = bias + (size_t)e * NDIM;
    if (FIRST) {
#pragma unroll
        for (int mt = 0; mt < 4; mt++) {
#pragma unroll
            for (int hh = 0; hh < 2; hh++) {
                int r = rowBase + warpM * 64 + mt * 16 + (lane >> 2) + hh * 8;
#pragma unroll
                for (int nt = 0; nt < 8; nt++) {
                    int c = colBase + warpN * 64 + nt * 8 + (lane & 3) * 2;
                    float v0 = acc[mt][nt][hh * 2 + 0] + be[c];
                    float v1 = acc[mt][nt][hh * 2 + 1] + be[c + 1];
                    v0 = v0 > 0.f ? v0 : 0.f;
                    v1 = v1 > 0.f ? v1 : 0.f;
                    *(__half2*)&g_hbuf[(size_t)r * DIMH + c] = __floats2half2_rn(v0, v1);
                }
            }
        }
    } else {
#pragma unroll
        for (int mt = 0; mt < 4; mt++) {
#pragma unroll
            for (int hh = 0; hh < 2; hh++) {
                int slot = rowBase + warpM * 64 + mt * 16 + (lane >> 2) + hh * 8;
                int tokn = g_perm[slot];
                if (tokn < 0) continue;
                float w = g_gate[slot];
#pragma unroll
                for (int nt = 0; nt < 8; nt++) {
                    int c = colBase + warpN * 64 + nt * 8 + (lane & 3) * 2;
                    atomicAdd(&Out[(size_t)tokn * DIMO + c],
                              w * (acc[mt][nt][hh * 2 + 0] + be[c]));
                    atomicAdd(&Out[(size_t)tokn * DIMO + c + 1],
                              w * (acc[mt][nt][hh * 2 + 1] + be[c + 1]));
                }
            }
        }
    }
}

// ---------------- launch: fork converts onto a side stream (capture fork/join) ----------------
extern "C" void kernel_launch(void* const* d_in, const int* in_sizes, int n_in,
                              void* d_out, int out_size) {
    const float* x  = (const float*)d_in[0];
    const float* Wg = (const float*)d_in[1];
    const float* bg = (const float*)d_in[2];
    const float* W1 = (const float*)d_in[3];
    const float* b1 = (const float*)d_in[4];
    const float* W2 = (const float*)d_in[5];
    const float* b2 = (const float*)d_in[6];
    float* out = (float*)d_out;

    __half *xh, *w1h, *w2h;
    cudaGetSymbolAddress((void**)&xh,  g_xh);
    cudaGetSymbolAddress((void**)&w1h, g_w1h);
    cudaGetSymbolAddress((void**)&w2h, g_w2h);

    cudaFuncSetAttribute(k_gemm<DIMD, DIMH, true>,
                         cudaFuncAttributeMaxDynamicSharedMemorySize, SMEM_TOT);
    cudaFuncSetAttribute(k_gemm<DIMH, DIMO, false>,
                         cudaFuncAttributeMaxDynamicSharedMemorySize, SMEM_TOT);

    cudaStream_t s1;
    cudaStreamCreate(&s1);
    cudaEvent_t e0, e1, e2;
    cudaEventCreateWithFlags(&e0, cudaEventDisableTiming);
    cudaEventCreateWithFlags(&e1, cudaEventDisableTiming);
    cudaEventCreateWithFlags(&e2, cudaEventDisableTiming);

    // main stream: init + routing
    k_init<<<(N_TOK * DIMO / 4 + 255) / 256, 256>>>(out);
    cudaEventRecord(e0, 0);

    // side stream: converts (x, W1, W2) — overlap with gate/route/gemm1
    cudaStreamWaitEvent(s1, e0, 0);
    {
        int n8x = N_TOK * DIMD / 8;
        k_cvt<<<(n8x + 255) / 256, 256, 0, s1>>>((const float4*)x, (uint4*)xh, n8x);
        int n8w = NEXP * DIMD * DIMH / 8;
        k_cvt<<<(n8w + 255) / 256, 256, 0, s1>>>((const float4*)W1, (uint4*)w1h, n8w);
        cudaEventRecord(e1, s1);
        k_cvt<<<(n8w + 255) / 256, 256, 0, s1>>>((const float4*)W2, (uint4*)w2h, n8w);
        cudaEventRecord(e2, s1);
    }

    k_gate<<<N_TOK / 8, 256>>>(x, Wg, bg);
    k_offsets<<<1, 1>>>();
    k_scatter<<<(N_TOK * 2 + 255) / 256, 256>>>();

    cudaStreamWaitEvent(0, e1, 0);   // need xh + w1h
    k_gemm<DIMD, DIMH, true ><<<dim3(DIMH / BN, MAXTILES), 128, SMEM_TOT>>>(w1h, b1, nullptr);
    cudaStreamWaitEvent(0, e2, 0);   // need w2h
    k_gemm<DIMH, DIMO, false><<<dim3(DIMO / BN, MAXTILES), 128, SMEM_TOT>>>(w2h, b2, out);
}

// round 17
// speedup vs baseline: 2.0358x; 1.0160x over previous
#include <cuda_runtime.h>
#include <cuda_fp16.h>
#include <cstdint>

#define N_TOK 8192
#define DIMD  1024
#define DIMH  4096
#define DIMO  1024
#define NEXP  8
#define TEMPR 2.718281828459045f

#define MAXSLOTS 17408
#define MAXTILES 136

#define BM 128
#define BN 128
#define BK 64
#define NSTAGE 3
#define STG_A_BYTES (BM * BK * 2)          // 16384 (A: 128 rows x 128B)
#define STG_B_BYTES (BK * BN * 2)          // 16384 (B: 64 k-rows x 256B)
#define STG_BYTES   (STG_A_BYTES + STG_B_BYTES)
#define SMEM_TOT    (NSTAGE * STG_BYTES)   // 98304

// ---------------- device scratch (static) ----------------
__device__ __half g_hbuf[(size_t)MAXSLOTS * DIMH];
__device__ float  g_obuf[(size_t)MAXSLOTS * DIMO];      // weighted per-slot GEMM2 output
__device__ __half g_xh  [(size_t)N_TOK * DIMD];
__device__ __half g_w1h [(size_t)NEXP * DIMD * DIMH];
__device__ __half g_w2h [(size_t)NEXP * DIMH * DIMO];
__device__ int   g_perm[MAXSLOTS];
__device__ float g_gate[MAXSLOTS];
__device__ int   g_tope[N_TOK * 2];
__device__ float g_topw[N_TOK * 2];
__device__ int   g_aslot[N_TOK * 2];                    // assignment -> slot
__device__ int   g_cnt[NEXP];
__device__ int   g_cur[NEXP];
__device__ int   g_off[NEXP];
__device__ int   g_texp[MAXTILES];

__device__ __forceinline__ uint32_t smem_u32(const void* p) {
    uint32_t a;
    asm("{ .reg .u64 t; cvta.to.shared.u64 t, %1; cvt.u32.u64 %0, t; }" : "=r"(a) : "l"(p));
    return a;
}
#define CPA16(dst, src) \
    asm volatile("cp.async.cg.shared.global [%0], [%1], 16;" :: "r"(dst), "l"(src))
#define CPA_COMMIT() asm volatile("cp.async.commit_group;" ::: "memory")
#define CPA_WAIT1()  asm volatile("cp.async.wait_group 1;" ::: "memory")
#define CPA_WAIT0()  asm volatile("cp.async.wait_group 0;" ::: "memory")
#define LDSM4(r, a) \
    asm volatile("ldmatrix.sync.aligned.m8n8.x4.shared.b16 {%0,%1,%2,%3}, [%4];" \
        : "=r"((r)[0]), "=r"((r)[1]), "=r"((r)[2]), "=r"((r)[3]) : "r"(a))
#define LDSM4T(r, a) \
    asm volatile("ldmatrix.sync.aligned.m8n8.x4.trans.shared.b16 {%0,%1,%2,%3}, [%4];" \
        : "=r"((r)[0]), "=r"((r)[1]), "=r"((r)[2]), "=r"((r)[3]) : "r"(a))

// ---------------- init: counters, perm/gate ----------------
__global__ void k_init() {
    int i = blockIdx.x * blockDim.x + threadIdx.x;
    if (i < MAXSLOTS) { g_perm[i] = -1; g_gate[i] = 0.f; }
    if (i < NEXP)     { g_cnt[i] = 0; g_cur[i] = 0; }
}

// ---------------- streaming convert fp32 -> fp16 ----------------
__global__ void k_cvt(const float4* __restrict__ in, uint4* __restrict__ out, int n8) {
    int i = blockIdx.x * blockDim.x + threadIdx.x;
    if (i >= n8) return;
    float4 a = in[2 * i], b = in[2 * i + 1];
    __half2 h[4];
    h[0] = __floats2half2_rn(a.x, a.y);
    h[1] = __floats2half2_rn(a.z, a.w);
    h[2] = __floats2half2_rn(b.x, b.y);
    h[3] = __floats2half2_rn(b.z, b.w);
    out[i] = *(uint4*)h;
}

// ---------------- routing ----------------
__global__ void k_gate(const float* __restrict__ x, const float* __restrict__ Wg,
                       const float* __restrict__ bg) {
    int lane = threadIdx.x & 31;
    int tok  = blockIdx.x * 8 + (threadIdx.x >> 5);
    float acc[NEXP];
#pragma unroll
    for (int e = 0; e < NEXP; e++) acc[e] = 0.f;
    const float* xr = x + (size_t)tok * DIMD;
    for (int d = lane; d < DIMD; d += 32) {
        float xv = xr[d];
        const float4* wg = (const float4*)(Wg + d * NEXP);
        float4 w0 = wg[0], w1 = wg[1];
        acc[0] += xv * w0.x; acc[1] += xv * w0.y; acc[2] += xv * w0.z; acc[3] += xv * w0.w;
        acc[4] += xv * w1.x; acc[5] += xv * w1.y; acc[6] += xv * w1.z; acc[7] += xv * w1.w;
    }
#pragma unroll
    for (int e = 0; e < NEXP; e++) {
#pragma unroll
        for (int o = 16; o > 0; o >>= 1) acc[e] += __shfl_xor_sync(0xffffffffu, acc[e], o);
    }
    if (lane == 0) {
        float s[NEXP];
#pragma unroll
        for (int e = 0; e < NEXP; e++) s[e] = (acc[e] + bg[e]) * (1.0f / TEMPR);
        int i1 = 0;
#pragma unroll
        for (int e = 1; e < NEXP; e++) if (s[e] > s[i1]) i1 = e;
        int i2 = (i1 == 0) ? 1 : 0;
#pragma unroll
        for (int e = 0; e < NEXP; e++) if (e != i1 && s[e] > s[i2]) i2 = e;
        float m = s[i1];
        float denom = 0.f;
#pragma unroll
        for (int e = 0; e < NEXP; e++) denom += expf(s[e] - m);
        float p1 = expf(s[i1] - m) / denom;
        float p2 = expf(s[i2] - m) / denom;
        float inv = 1.f / (p1 + p2 + 1e-8f);
        g_tope[tok * 2 + 0] = i1; g_topw[tok * 2 + 0] = p1 * inv;
        g_tope[tok * 2 + 1] = i2; g_topw[tok * 2 + 1] = p2 * inv;
        atomicAdd(&g_cnt[i1], 1);
        atomicAdd(&g_cnt[i2], 1);
    }
}

__global__ void k_offsets() {
    int tileE[MAXTILES];
    int run = 0;
    for (int e = 0; e < NEXP; e++) {
        g_off[e] = run;
        int ntile = (g_cnt[e] + BM - 1) / BM;
        for (int t = 0; t < ntile; t++) tileE[run / BM + t] = e;
        run += ntile * BM;
    }
    int used = run / BM;
    for (int t = 0; t < MAXTILES; t++) g_texp[t] = (t < used) ? tileE[t] : -1;
}

__global__ void k_scatter() {
    int i = blockIdx.x * blockDim.x + threadIdx.x;
    if (i >= N_TOK * 2) return;
    int e = g_tope[i];
    int pos = atomicAdd(&g_cur[e], 1);
    int slot = g_off[e] + pos;
    g_perm[slot] = i >> 1;
    g_gate[slot] = g_topw[i];
    g_aslot[i] = slot;
}

// ---------------- combine: out[tok] = obuf[slot0] + obuf[slot1] ----------------
__global__ void k_combine(float4* __restrict__ out) {
    int idx = blockIdx.x * blockDim.x + threadIdx.x;      // one float4
    int tok = idx >> 8;                                    // DIMO/4 = 256 per token
    int c4  = idx & 255;
    int s0 = g_aslot[tok * 2 + 0];
    int s1 = g_aslot[tok * 2 + 1];
    const float4* r0 = (const float4*)&g_obuf[(size_t)s0 * DIMO];
    const float4* r1 = (const float4*)&g_obuf[(size_t)s1 * DIMO];
    float4 a = r0[c4], b = r1[c4];
    out[idx] = make_float4(a.x + b.x, a.y + b.y, a.z + b.z, a.w + b.w);
}

// ---------------- fp16 grouped GEMM (R16 mainloop, vectorized epilogues) ----------------
template<int KDIM, int NDIM, bool FIRST>
__global__ __launch_bounds__(128, 2) void k_gemm(
    const __half* __restrict__ Bh,
    const float* __restrict__ bias,
    float* __restrict__ Out)
{
    extern __shared__ char smem[];
    const int tileM = blockIdx.y;
    const int e = g_texp[tileM];
    if (e < 0) return;
    const int rowBase = tileM * BM;
    const int colBase = blockIdx.x * BN;

    const uint32_t sb = smem_u32(smem);
    const int tid  = threadIdx.x;
    const int lane = tid & 31;
    const int warp = tid >> 5;
    const int warpM = warp & 1;
    const int warpN = warp >> 1;

    const __half* A = FIRST ? g_xh : g_hbuf;
    const __half* Bmat = Bh + (size_t)e * KDIM * NDIM;

    const int trow = tid >> 3;
    const int tch  = tid & 7;
    const __half* aSrc[8];
#pragma unroll
    for (int i = 0; i < 8; i++) {
        int slot = rowBase + trow + 16 * i;
        int src;
        if (FIRST) { int t = g_perm[slot]; src = (t < 0) ? 0 : t; }
        else       { src = slot; }
        aSrc[i] = A + (size_t)src * KDIM + tch * 8;
    }
    uint32_t dOffA[8];
#pragma unroll
    for (int i = 0; i < 8; i++) {
        int row = trow + 16 * i;
        dOffA[i] = row * 128 + ((tch ^ (row & 7)) << 4);
    }

    const int bR8 = tid >> 4;
    const int bC  = tid & 15;
    const __half* bSrc[8];
    uint32_t dOffB[8];
#pragma unroll
    for (int i = 0; i < 8; i++) {
        int krow = bR8 + 8 * i;
        bSrc[i] = Bmat + (size_t)krow * NDIM + colBase + bC * 8;
        dOffB[i] = krow * 256 + ((bC ^ (krow & 7)) << 4);
    }

    const int laneRowOff = (lane & 7) + ((lane >> 3) & 1) * 8;
    const int csel = lane >> 4;
    const int xr   = lane & 7;
    uint32_t aRB[4];
#pragma unroll
    for (int mt = 0; mt < 4; mt++) aRB[mt] = (warpM * 64 + mt * 16 + laneRowOff) * 128;
    uint32_t bCh[4];
#pragma unroll
    for (int np = 0; np < 4; np++)
        bCh[np] = (uint32_t)((warpN * 8 + ((np * 2 + csel) ^ xr)) << 4);
    const uint32_t bRowOff = (uint32_t)(laneRowOff * 256);

    float acc[4][8][4];
#pragma unroll
    for (int mt = 0; mt < 4; mt++)
#pragma unroll
        for (int nt = 0; nt < 8; nt++)
#pragma unroll
            for (int i = 0; i < 4; i++) acc[mt][nt][i] = 0.f;

    const int NKB = KDIM / BK;

#pragma unroll
    for (int s = 0; s < NSTAGE - 1; s++) {
        uint32_t stA = sb + s * STG_BYTES;
        uint32_t stB = stA + STG_A_BYTES;
#pragma unroll
        for (int i = 0; i < 8; i++) CPA16(stA + dOffA[i], aSrc[i] + s * BK);
#pragma unroll
        for (int i = 0; i < 8; i++) CPA16(stB + dOffB[i], bSrc[i] + (size_t)s * BK * NDIM);
        CPA_COMMIT();
    }

    int buf = 0;
    for (int kb = 0; kb < NKB; kb++) {
        CPA_WAIT1();
        __syncthreads();
        if (kb + 2 < NKB) {
            int nb = buf + 2; if (nb >= NSTAGE) nb -= NSTAGE;
            uint32_t stA = sb + nb * STG_BYTES;
            uint32_t stB = stA + STG_A_BYTES;
            const int k0 = (kb + 2) * BK;
#pragma unroll
            for (int i = 0; i < 8; i++) CPA16(stA + dOffA[i], aSrc[i] + k0);
#pragma unroll
            for (int i = 0; i < 8; i++) CPA16(stB + dOffB[i], bSrc[i] + (size_t)k0 * NDIM);
        }
        CPA_COMMIT();

        const uint32_t stA = sb + buf * STG_BYTES;
        const uint32_t stB = stA + STG_A_BYTES;
#pragma unroll
        for (int ks = 0; ks < 4; ks++) {
            const uint32_t swA = (uint32_t)(((2 * ks + csel) ^ xr) << 4);
            const uint32_t rB  = (uint32_t)(ks * 16 * 256) + bRowOff;
            unsigned af[4][4], bf[4][4];
#pragma unroll
            for (int mt = 0; mt < 4; mt++) LDSM4(af[mt], stA + aRB[mt] + swA);
#pragma unroll
            for (int np = 0; np < 4; np++) LDSM4T(bf[np], stB + rB + bCh[np]);
#pragma unroll
            for (int mt = 0; mt < 4; mt++)
#pragma unroll
                for (int nt = 0; nt < 8; nt++) {
                    const unsigned b0 = bf[nt >> 1][(nt & 1) * 2];
                    const unsigned b1 = bf[nt >> 1][(nt & 1) * 2 + 1];
                    asm volatile(
                        "mma.sync.aligned.m16n8k16.row.col.f32.f16.f16.f32 "
                        "{%0,%1,%2,%3},{%4,%5,%6,%7},{%8,%9},{%0,%1,%2,%3};"
                        : "+f"(acc[mt][nt][0]), "+f"(acc[mt][nt][1]),
                          "+f"(acc[mt][nt][2]), "+f"(acc[mt][nt][3])
                        : "r"(af[mt][0]), "r"(af[mt][1]), "r"(af[mt][2]), "r"(af[mt][3]),
                          "r"(b0), "r"(b1));
                }
        }
        buf++; if (buf == NSTAGE) buf = 0;
    }
    CPA_WAIT0();
    __syncthreads();    // stage buffers free for epilogue reuse

    // ---------------- vectorized epilogues (smem remap -> 16B stores) ----------------
    const float* be = bias + (size_t)e * NDIM + colBase + warpN * 64;
    if (FIRST) {
        // warp-private 64 x 72-half tile (144B rows; bank = 4r + q, conflict-free)
        __half* wt = (__half*)(smem + warp * 9216);
#pragma unroll
        for (int mt = 0; mt < 4; mt++) {
#pragma unroll
            for (int hh = 0; hh < 2; hh++) {
                int r = mt * 16 + hh * 8 + (lane >> 2);
#pragma unroll
                for (int nt = 0; nt < 8; nt++) {
                    int c = nt * 8 + (lane & 3) * 2;
                    float v0 = acc[mt][nt][hh * 2 + 0] + be[c];
                    float v1 = acc[mt][nt][hh * 2 + 1] + be[c + 1];
                    v0 = v0 > 0.f ? v0 : 0.f;
                    v1 = v1 > 0.f ? v1 : 0.f;
                    *(__half2*)&wt[r * 72 + c] = __floats2half2_rn(v0, v1);
                }
            }
        }
        __syncwarp();
#pragma unroll
        for (int i = 0; i < 16; i++) {
            int idx = lane + 32 * i;           // 0..511 = 64 rows x 8 chunks
            int r = idx >> 3, ch = idx & 7;
            uint4 v = *(uint4*)&wt[r * 72 + ch * 8];
            int grow = rowBase + warpM * 64 + r;
            *(uint4*)&g_hbuf[(size_t)grow * DIMH + colBase + warpN * 64 + ch * 8] = v;
        }
    } else {
        // weighted per-slot write to g_obuf; combine kernel sums the 2 slots/token.
        float* wt = (float*)(smem + warp * 17408);   // 64 x 68-float tile
        int slotL  = rowBase + warpM * 64 + lane;    // rows lane, lane+32
        float gA = g_gate[slotL];
        float gB = g_gate[slotL + 32];
#pragma unroll
        for (int mt = 0; mt < 4; mt++) {
#pragma unroll
            for (int hh = 0; hh < 2; hh++) {
                int r = mt * 16 + hh * 8 + (lane >> 2);
                float w = __shfl_sync(0xffffffffu, (mt < 2) ? gA : gB,
                                      (mt & 1) * 16 + hh * 8 + (lane >> 2));
#pragma unroll
                for (int nt = 0; nt < 8; nt++) {
                    int c = nt * 8 + (lane & 3) * 2;
                    wt[r * 68 + c]     = w * (acc[mt][nt][hh * 2 + 0] + be[c]);
                    wt[r * 68 + c + 1] = w * (acc[mt][nt][hh * 2 + 1] + be[c + 1]);
                }
            }
        }
        __syncwarp();
#pragma unroll
        for (int i = 0; i < 32; i++) {
            int idx = lane + 32 * i;           // 0..1023 = 64 rows x 16 chunks
            int r = idx >> 4, ch = idx & 15;
            float4 v = *(float4*)&wt[r * 68 + ch * 4];
            int slot = rowBase + warpM * 64 + r;
            *(float4*)&g_obuf[(size_t)slot * DIMO + colBase + warpN * 64 + ch * 4] = v;
        }
    }
}

// ---------------- launch ----------------
extern "C" void kernel_launch(void* const* d_in, const int* in_sizes, int n_in,
                              void* d_out, int out_size) {
    const float* x  = (const float*)d_in[0];
    const float* Wg = (const float*)d_in[1];
    const float* bg = (const float*)d_in[2];
    const float* W1 = (const float*)d_in[3];
    const float* b1 = (const float*)d_in[4];
    const float* W2 = (const float*)d_in[5];
    const float* b2 = (const float*)d_in[6];
    float* out = (float*)d_out;

    __half *xh, *w1h, *w2h;
    cudaGetSymbolAddress((void**)&xh,  g_xh);
    cudaGetSymbolAddress((void**)&w1h, g_w1h);
    cudaGetSymbolAddress((void**)&w2h, g_w2h);

    cudaFuncSetAttribute(k_gemm<DIMD, DIMH, true>,
                         cudaFuncAttributeMaxDynamicSharedMemorySize, SMEM_TOT);
    cudaFuncSetAttribute(k_gemm<DIMH, DIMO, false>,
                         cudaFuncAttributeMaxDynamicSharedMemorySize, SMEM_TOT);

    cudaStream_t s1;
    cudaStreamCreate(&s1);
    cudaEvent_t e0, e1, e2;
    cudaEventCreateWithFlags(&e0, cudaEventDisableTiming);
    cudaEventCreateWithFlags(&e1, cudaEventDisableTiming);
    cudaEventCreateWithFlags(&e2, cudaEventDisableTiming);

    k_init<<<(MAXSLOTS + 255) / 256, 256>>>();
    cudaEventRecord(e0, 0);

    cudaStreamWaitEvent(s1, e0, 0);
    {
        int n8x = N_TOK * DIMD / 8;
        k_cvt<<<(n8x + 255) / 256, 256, 0, s1>>>((const float4*)x, (uint4*)xh, n8x);
        int n8w = NEXP * DIMD * DIMH / 8;
        k_cvt<<<(n8w + 255) / 256, 256, 0, s1>>>((const float4*)W1, (uint4*)w1h, n8w);
        cudaEventRecord(e1, s1);
        k_cvt<<<(n8w + 255) / 256, 256, 0, s1>>>((const float4*)W2, (uint4*)w2h, n8w);
        cudaEventRecord(e2, s1);
    }

    k_gate<<<N_TOK / 8, 256>>>(x, Wg, bg);
    k_offsets<<<1, 1>>>();
    k_scatter<<<(N_TOK * 2 + 255) / 256, 256>>>();

    cudaStreamWaitEvent(0, e1, 0);
    k_gemm<DIMD, DIMH, true ><<<dim3(DIMH / BN, MAXTILES), 128, SMEM_TOT>>>(w1h, b1, nullptr);
    cudaStreamWaitEvent(0, e2, 0);
    k_gemm<DIMH, DIMO, false><<<dim3(DIMO / BN, MAXTILES), 128, SMEM_TOT>>>(w2h, b2, out);
    k_combine<<<N_TOK * DIMO / 4 / 256, 256>>>((float4*)out);
}